// round 1
// baseline (speedup 1.0000x reference)
#include <cuda_runtime.h>
#include <math.h>

#define Ldim 2048
#define Nb   4
#define E    768
#define H    12
#define HD   64
#define Mrows (Ldim*Nb)     /* 8192 */
#define EE   (E*E)          /* 589824 */

// ---------------- scratch (static device globals; no runtime allocation) ----
__device__ float g_weff[4*EE];   // fused W + up@down for q,k,v,out
__device__ float g_q[Mrows*E];
__device__ float g_k[Mrows*E];
__device__ float g_v[Mrows*E];
__device__ float g_o[Mrows*E];

// ---------------- W_eff = W + (ALPHA/R=1.0) * up @ down ---------------------
__global__ void weff_kernel(const float* __restrict__ inW,
                            const float* __restrict__ outW,
                            const float* __restrict__ qd, const float* __restrict__ qu,
                            const float* __restrict__ kd, const float* __restrict__ ku,
                            const float* __restrict__ vd, const float* __restrict__ vu,
                            const float* __restrict__ od, const float* __restrict__ ou)
{
    int z = blockIdx.y;
    int idx = blockIdx.x * 256 + threadIdx.x;          // < EE
    int e = idx / E;
    int k = idx - e * E;
    const float* W  = (z < 3) ? (inW + z * EE) : outW;
    const float* dn = (z == 0) ? qd : (z == 1) ? kd : (z == 2) ? vd : od;
    const float* up = (z == 0) ? qu : (z == 1) ? ku : (z == 2) ? vu : ou;
    float s = 0.f;
#pragma unroll
    for (int r = 0; r < 16; r++) s += up[e * 16 + r] * dn[r * E + k];
    g_weff[z * EE + idx] = W[idx] + s;                 // LORA_SCALE == 1.0
}

// ---------------- 128x128x8 register-tiled fp32 GEMM ------------------------
// y[m,e] = (sum_k x[m,k]*W[e,k] + bias[e]) * (z==qz ? 0.125 : 1)
__global__ void __launch_bounds__(256, 2) gemm_proj(
    const float* __restrict__ x0, const float* __restrict__ x1, const float* __restrict__ x2,
    const float* __restrict__ Wbase, const float* __restrict__ bias_base,
    float* __restrict__ y0, float* __restrict__ y1, float* __restrict__ y2,
    int qz)
{
    int z = blockIdx.z;
    const float* x = (z == 0) ? x0 : (z == 1) ? x1 : x2;
    float*       y = (z == 0) ? y0 : (z == 1) ? y1 : y2;
    const float* W = Wbase + (size_t)z * EE;
    const float* bias = bias_base + z * E;

    int m0 = blockIdx.y * 128;
    int e0 = blockIdx.x * 128;

    __shared__ float As[8][128];
    __shared__ float Bs[8][128];

    float acc[8][8];
#pragma unroll
    for (int i = 0; i < 8; i++)
#pragma unroll
        for (int j = 0; j < 8; j++) acc[i][j] = 0.f;

    int tid = threadIdx.x;
    int lr = tid >> 1;            // 0..127 : tile row being loaded
    int lc = (tid & 1) * 4;       // 0 or 4 : k offset being loaded
    int ty = tid >> 4, tx = tid & 15;

    for (int k0 = 0; k0 < E; k0 += 8) {
        float4 av = *(const float4*)(x + (size_t)(m0 + lr) * E + k0 + lc);
        float4 bv = *(const float4*)(W + (size_t)(e0 + lr) * E + k0 + lc);
        __syncthreads();
        As[lc + 0][lr] = av.x; As[lc + 1][lr] = av.y; As[lc + 2][lr] = av.z; As[lc + 3][lr] = av.w;
        Bs[lc + 0][lr] = bv.x; Bs[lc + 1][lr] = bv.y; Bs[lc + 2][lr] = bv.z; Bs[lc + 3][lr] = bv.w;
        __syncthreads();
#pragma unroll
        for (int kt = 0; kt < 8; kt++) {
            float a[8], b[8];
            float4 t;
            t = *(const float4*)&As[kt][ty * 4];      a[0]=t.x; a[1]=t.y; a[2]=t.z; a[3]=t.w;
            t = *(const float4*)&As[kt][64 + ty * 4]; a[4]=t.x; a[5]=t.y; a[6]=t.z; a[7]=t.w;
            t = *(const float4*)&Bs[kt][tx * 4];      b[0]=t.x; b[1]=t.y; b[2]=t.z; b[3]=t.w;
            t = *(const float4*)&Bs[kt][64 + tx * 4]; b[4]=t.x; b[5]=t.y; b[6]=t.z; b[7]=t.w;
#pragma unroll
            for (int i = 0; i < 8; i++)
#pragma unroll
                for (int j = 0; j < 8; j++) acc[i][j] += a[i] * b[j];
        }
    }

    float qs = (z == qz) ? 0.125f : 1.0f;   // fold 1/sqrt(HD) into q
#pragma unroll
    for (int i = 0; i < 8; i++) {
        int row = m0 + ((i < 4) ? (ty * 4 + i) : (64 + ty * 4 + i - 4));
#pragma unroll
        for (int j = 0; j < 8; j++) {
            int col = e0 + ((j < 4) ? (tx * 4 + j) : (64 + tx * 4 + j - 4));
            y[(size_t)row * E + col] = (acc[i][j] + bias[col]) * qs;
        }
    }
}

// ---------------- flash attention, fp32, BM=BS=64 ---------------------------
// grid: (L/64, N*H), 256 threads. q pre-scaled by 1/8 at projection.
__global__ void __launch_bounds__(256) attn_kernel()
{
    extern __shared__ float sm[];
    float* qs_t = sm;                 // [d][m] 64x64
    float* ks_t = sm + 4096;          // [d][s] 64x64
    float* vs   = sm + 8192;          // [s][d] 64x64
    float* sP   = sm + 12288;         // [m][65]
    float* m_s  = sm + 12288 + 64 * 65;
    float* l_s  = m_s + 64;
    float* c_s  = l_s + 64;

    int tid = threadIdx.x;
    int bh = blockIdx.y;
    int n = bh / H, h = bh - n * H;
    int l0 = blockIdx.x * 64;
    int ty = tid >> 4, tx = tid & 15;

    // load q tile transposed: qs_t[d][m]
    {
        int m = tid >> 2, seg = tid & 3;
        const float* src = g_q + ((size_t)(l0 + m) * Nb + n) * E + h * HD;
#pragma unroll
        for (int q4 = 0; q4 < 4; q4++) {
            int d = seg * 16 + q4 * 4;
            float4 v = *(const float4*)(src + d);
            qs_t[(d + 0) * 64 + m] = v.x;
            qs_t[(d + 1) * 64 + m] = v.y;
            qs_t[(d + 2) * 64 + m] = v.z;
            qs_t[(d + 3) * 64 + m] = v.w;
        }
    }
    if (tid < 64) { m_s[tid] = -INFINITY; l_s[tid] = 0.f; }

    float acc[4][4];
#pragma unroll
    for (int i = 0; i < 4; i++)
#pragma unroll
        for (int j = 0; j < 4; j++) acc[i][j] = 0.f;

    for (int s0 = 0; s0 < Ldim; s0 += 64) {
        __syncthreads();   // previous tile fully consumed; q/m/l init visible
        // load K (transposed) and V tiles
        {
            int s = tid >> 2, seg = tid & 3;
            const float* ksrc = g_k + ((size_t)(s0 + s) * Nb + n) * E + h * HD;
            const float* vsrc = g_v + ((size_t)(s0 + s) * Nb + n) * E + h * HD;
#pragma unroll
            for (int q4 = 0; q4 < 4; q4++) {
                int d = seg * 16 + q4 * 4;
                float4 kv = *(const float4*)(ksrc + d);
                ks_t[(d + 0) * 64 + s] = kv.x;
                ks_t[(d + 1) * 64 + s] = kv.y;
                ks_t[(d + 2) * 64 + s] = kv.z;
                ks_t[(d + 3) * 64 + s] = kv.w;
                *(float4*)&vs[s * 64 + d] = *(const float4*)(vsrc + d);
            }
        }
        __syncthreads();

        // phase 1: S = q @ k^T  (each thread 4x4)
        float sacc[4][4];
#pragma unroll
        for (int i = 0; i < 4; i++)
#pragma unroll
            for (int j = 0; j < 4; j++) sacc[i][j] = 0.f;
#pragma unroll 16
        for (int d = 0; d < 64; d++) {
            float4 a = *(const float4*)&qs_t[d * 64 + ty * 4];
            float4 b = *(const float4*)&ks_t[d * 64 + tx * 4];
            float av[4] = {a.x, a.y, a.z, a.w};
            float bv[4] = {b.x, b.y, b.z, b.w};
#pragma unroll
            for (int i = 0; i < 4; i++)
#pragma unroll
                for (int j = 0; j < 4; j++) sacc[i][j] += av[i] * bv[j];
        }
#pragma unroll
        for (int i = 0; i < 4; i++)
#pragma unroll
            for (int j = 0; j < 4; j++)
                sP[(ty * 4 + i) * 65 + tx * 4 + j] = sacc[i][j];
        __syncthreads();

        // phase 2: online softmax (4 threads per row)
        {
            int row = tid >> 2, part = tid & 3;
            float mo = m_s[row];
            float tmax = -INFINITY;
#pragma unroll
            for (int c = 0; c < 16; c++)
                tmax = fmaxf(tmax, sP[row * 65 + part * 16 + c]);
            tmax = fmaxf(tmax, __shfl_xor_sync(0xffffffffu, tmax, 1));
            tmax = fmaxf(tmax, __shfl_xor_sync(0xffffffffu, tmax, 2));
            float mn = fmaxf(mo, tmax);
            float corr = __expf(mo - mn);
            float lsum = 0.f;
#pragma unroll
            for (int c = 0; c < 16; c++) {
                float p = __expf(sP[row * 65 + part * 16 + c] - mn);
                sP[row * 65 + part * 16 + c] = p;
                lsum += p;
            }
            lsum += __shfl_xor_sync(0xffffffffu, lsum, 1);
            lsum += __shfl_xor_sync(0xffffffffu, lsum, 2);
            if (part == 0) {
                m_s[row] = mn;
                l_s[row] = l_s[row] * corr + lsum;
                c_s[row] = corr;
            }
        }
        __syncthreads();

        // phase 3: O = O*corr + P @ V
        float cr[4];
#pragma unroll
        for (int i = 0; i < 4; i++) cr[i] = c_s[ty * 4 + i];
#pragma unroll
        for (int i = 0; i < 4; i++)
#pragma unroll
            for (int j = 0; j < 4; j++) acc[i][j] *= cr[i];
#pragma unroll 16
        for (int s = 0; s < 64; s++) {
            float4 b = *(const float4*)&vs[s * 64 + tx * 4];
            float a0 = sP[(ty * 4 + 0) * 65 + s];
            float a1 = sP[(ty * 4 + 1) * 65 + s];
            float a2 = sP[(ty * 4 + 2) * 65 + s];
            float a3 = sP[(ty * 4 + 3) * 65 + s];
            acc[0][0] += a0 * b.x; acc[0][1] += a0 * b.y; acc[0][2] += a0 * b.z; acc[0][3] += a0 * b.w;
            acc[1][0] += a1 * b.x; acc[1][1] += a1 * b.y; acc[1][2] += a1 * b.z; acc[1][3] += a1 * b.w;
            acc[2][0] += a2 * b.x; acc[2][1] += a2 * b.y; acc[2][2] += a2 * b.z; acc[2][3] += a2 * b.w;
            acc[3][0] += a3 * b.x; acc[3][1] += a3 * b.y; acc[3][2] += a3 * b.z; acc[3][3] += a3 * b.w;
        }
    }

    // write o back in (L, N, E) layout: e = h*64 + d
#pragma unroll
    for (int i = 0; i < 4; i++) {
        int row = ty * 4 + i;
        float inv = 1.f / l_s[row];
        float* dst = g_o + ((size_t)(l0 + row) * Nb + n) * E + h * HD + tx * 4;
        dst[0] = acc[i][0] * inv;
        dst[1] = acc[i][1] * inv;
        dst[2] = acc[i][2] * inv;
        dst[3] = acc[i][3] * inv;
    }
}

// ---------------- launcher ---------------------------------------------------
extern "C" void kernel_launch(void* const* d_in, const int* in_sizes, int n_in,
                              void* d_out, int out_size)
{
    const float* query = (const float*)d_in[0];
    const float* key   = (const float*)d_in[1];
    const float* value = (const float*)d_in[2];
    const float* in_w  = (const float*)d_in[3];
    const float* in_b  = (const float*)d_in[4];
    const float* q_dn  = (const float*)d_in[5];
    const float* q_up  = (const float*)d_in[6];
    const float* k_dn  = (const float*)d_in[7];
    const float* k_up  = (const float*)d_in[8];
    const float* v_dn  = (const float*)d_in[9];
    const float* v_up  = (const float*)d_in[10];
    const float* out_w = (const float*)d_in[11];
    const float* out_b = (const float*)d_in[12];
    const float* o_dn  = (const float*)d_in[13];
    const float* o_up  = (const float*)d_in[14];

    float *p_weff, *p_q, *p_k, *p_v, *p_o;
    cudaGetSymbolAddress((void**)&p_weff, g_weff);
    cudaGetSymbolAddress((void**)&p_q, g_q);
    cudaGetSymbolAddress((void**)&p_k, g_k);
    cudaGetSymbolAddress((void**)&p_v, g_v);
    cudaGetSymbolAddress((void**)&p_o, g_o);

    const int attn_smem = (4096 * 3 + 64 * 65 + 192) * 4;  // 66560 B
    cudaFuncSetAttribute(attn_kernel,
                         cudaFuncAttributeMaxDynamicSharedMemorySize, attn_smem);

    // 1) fold LoRA into effective weights
    weff_kernel<<<dim3(EE / 256, 4), 256>>>(in_w, out_w,
                                            q_dn, q_up, k_dn, k_up,
                                            v_dn, v_up, o_dn, o_up);
    // 2) q,k,v projections (q pre-scaled by 1/8)
    gemm_proj<<<dim3(E / 128, Mrows / 128, 3), 256>>>(
        query, key, value, p_weff, in_b, p_q, p_k, p_v, /*qz=*/0);
    // 3) attention
    attn_kernel<<<dim3(Ldim / 64, Nb * H), 256, attn_smem>>>();
    // 4) output projection -> d_out
    gemm_proj<<<dim3(E / 128, Mrows / 128, 1), 256>>>(
        p_o, p_o, p_o, p_weff + 3 * (size_t)EE, out_b,
        (float*)d_out, (float*)d_out, (float*)d_out, /*qz=*/-1);
}

// round 4
// speedup vs baseline: 1.7267x; 1.7267x over previous
#include <cuda_runtime.h>
#include <cuda_bf16.h>
#include <math.h>
#include <stdint.h>

#define Ldim 2048
#define Nb   4
#define E    768
#define H    12
#define HD   64
#define BH   (Nb*H)         /* 48 */
#define Mrows (Ldim*Nb)     /* 8192 */
#define EE   (E*E)          /* 589824 */

// ---------------- scratch (static device globals; no runtime allocation) ----
__device__ float g_weff[4*EE];
__device__ float g_q[Mrows*E];
__device__ float g_k[Mrows*E];
__device__ float g_v[Mrows*E];
__device__ float g_o[Mrows*E];
// bf16 hi/lo split buffers: q,k as [bh][l][64]; v transposed as [bh][d][L]
__device__ __nv_bfloat16 g_qh[BH*Ldim*HD], g_ql[BH*Ldim*HD];
__device__ __nv_bfloat16 g_kh[BH*Ldim*HD], g_kl[BH*Ldim*HD];
__device__ __nv_bfloat16 g_vth[BH*HD*Ldim], g_vtl[BH*HD*Ldim];

// ============================ helpers ========================================
__device__ __forceinline__ uint32_t smem_u32(const void* p) {
    uint32_t a;
    asm("{ .reg .u64 t; cvta.to.shared.u64 t, %1; cvt.u32.u64 %0, t; }"
        : "=r"(a) : "l"(p));
    return a;
}
__device__ __forceinline__ float ex2f(float x) {
    float y; asm("ex2.approx.f32 %0, %1;" : "=f"(y) : "f"(x)); return y;
}
#define STS128(addr, r0, r1, r2, r3) \
    asm volatile("st.shared.v4.b32 [%0], {%1, %2, %3, %4};" \
                 :: "r"(addr), "r"(r0), "r"(r1), "r"(r2), "r"(r3) : "memory")

__device__ __forceinline__ void ldm_x4(uint32_t* r, uint32_t addr) {
    asm volatile("ldmatrix.sync.aligned.m8n8.x4.shared.b16 {%0,%1,%2,%3}, [%4];"
                 : "=r"(r[0]), "=r"(r[1]), "=r"(r[2]), "=r"(r[3]) : "r"(addr));
}
__device__ __forceinline__ void mma16816(float* c, const uint32_t* a,
                                         const uint32_t* b) {
    asm volatile(
        "mma.sync.aligned.m16n8k16.row.col.f32.bf16.bf16.f32 "
        "{%0,%1,%2,%3}, {%4,%5,%6,%7}, {%8,%9}, {%0,%1,%2,%3};"
        : "+f"(c[0]), "+f"(c[1]), "+f"(c[2]), "+f"(c[3])
        : "r"(a[0]), "r"(a[1]), "r"(a[2]), "r"(a[3]), "r"(b[0]), "r"(b[1]));
}
// split a pair of floats into bf16 hi and lo packed words (elem0 in low bits)
__device__ __forceinline__ void split2(float a, float b, uint32_t& hi, uint32_t& lo) {
    __nv_bfloat162 h = __floats2bfloat162_rn(a, b);
    float la = a - __bfloat162float(h.x);
    float lb = b - __bfloat162float(h.y);
    __nv_bfloat162 l = __floats2bfloat162_rn(la, lb);
    hi = *reinterpret_cast<uint32_t*>(&h);
    lo = *reinterpret_cast<uint32_t*>(&l);
}

// ---------------- W_eff = W + up @ down -------------------------------------
__global__ void weff_kernel(const float* __restrict__ inW,
                            const float* __restrict__ outW,
                            const float* __restrict__ qd, const float* __restrict__ qu,
                            const float* __restrict__ kd, const float* __restrict__ ku,
                            const float* __restrict__ vd, const float* __restrict__ vu,
                            const float* __restrict__ od, const float* __restrict__ ou)
{
    int z = blockIdx.y;
    int idx = blockIdx.x * 256 + threadIdx.x;
    int e = idx / E;
    int k = idx - e * E;
    const float* W  = (z < 3) ? (inW + z * EE) : outW;
    const float* dn = (z == 0) ? qd : (z == 1) ? kd : (z == 2) ? vd : od;
    const float* up = (z == 0) ? qu : (z == 1) ? ku : (z == 2) ? vu : ou;
    float s = 0.f;
#pragma unroll
    for (int r = 0; r < 16; r++) s += up[e * 16 + r] * dn[r * E + k];
    g_weff[z * EE + idx] = W[idx] + s;
}

// ---------------- 128x128x8 register-tiled fp32 GEMM ------------------------
__global__ void __launch_bounds__(256, 2) gemm_proj(
    const float* __restrict__ x0, const float* __restrict__ x1, const float* __restrict__ x2,
    const float* __restrict__ Wbase, const float* __restrict__ bias_base,
    float* __restrict__ y0, float* __restrict__ y1, float* __restrict__ y2,
    int qz)
{
    int z = blockIdx.z;
    const float* x = (z == 0) ? x0 : (z == 1) ? x1 : x2;
    float*       y = (z == 0) ? y0 : (z == 1) ? y1 : y2;
    const float* W = Wbase + (size_t)z * EE;
    const float* bias = bias_base + z * E;

    int m0 = blockIdx.y * 128;
    int e0 = blockIdx.x * 128;

    __shared__ float As[8][128];
    __shared__ float Bs[8][128];

    float acc[8][8];
#pragma unroll
    for (int i = 0; i < 8; i++)
#pragma unroll
        for (int j = 0; j < 8; j++) acc[i][j] = 0.f;

    int tid = threadIdx.x;
    int lr = tid >> 1;
    int lc = (tid & 1) * 4;
    int ty = tid >> 4, tx = tid & 15;

    for (int k0 = 0; k0 < E; k0 += 8) {
        float4 av = *(const float4*)(x + (size_t)(m0 + lr) * E + k0 + lc);
        float4 bv = *(const float4*)(W + (size_t)(e0 + lr) * E + k0 + lc);
        __syncthreads();
        As[lc + 0][lr] = av.x; As[lc + 1][lr] = av.y; As[lc + 2][lr] = av.z; As[lc + 3][lr] = av.w;
        Bs[lc + 0][lr] = bv.x; Bs[lc + 1][lr] = bv.y; Bs[lc + 2][lr] = bv.z; Bs[lc + 3][lr] = bv.w;
        __syncthreads();
#pragma unroll
        for (int kt = 0; kt < 8; kt++) {
            float a[8], b[8];
            float4 t;
            t = *(const float4*)&As[kt][ty * 4];      a[0]=t.x; a[1]=t.y; a[2]=t.z; a[3]=t.w;
            t = *(const float4*)&As[kt][64 + ty * 4]; a[4]=t.x; a[5]=t.y; a[6]=t.z; a[7]=t.w;
            t = *(const float4*)&Bs[kt][tx * 4];      b[0]=t.x; b[1]=t.y; b[2]=t.z; b[3]=t.w;
            t = *(const float4*)&Bs[kt][64 + tx * 4]; b[4]=t.x; b[5]=t.y; b[6]=t.z; b[7]=t.w;
#pragma unroll
            for (int i = 0; i < 8; i++)
#pragma unroll
                for (int j = 0; j < 8; j++) acc[i][j] += a[i] * b[j];
        }
    }

    float qs = (z == qz) ? 0.125f * 1.4426950408889634f : 1.0f; // fold scale*log2e into q
#pragma unroll
    for (int i = 0; i < 8; i++) {
        int row = m0 + ((i < 4) ? (ty * 4 + i) : (64 + ty * 4 + i - 4));
#pragma unroll
        for (int j = 0; j < 8; j++) {
            int col = e0 + ((j < 4) ? (tx * 4 + j) : (64 + tx * 4 + j - 4));
            y[(size_t)row * E + col] = (acc[i][j] + bias[col]) * qs;
        }
    }
}

// ---------------- prep: q,k -> bf16 hi/lo [bh][l][64] ------------------------
__global__ void __launch_bounds__(256) qk_prep()
{
    int z = blockIdx.z;
    size_t idx = (size_t)blockIdx.x * 256 + threadIdx.x;  // float4 index
    const float4* src = (const float4*)(z ? g_k : g_q);
    float4 v = src[idx];
    int e4 = (int)(idx % (E / 4));
    int ln = (int)(idx / (E / 4));          // l*Nb + nb
    int e = e4 * 4, h = e >> 6, d = e & 63;
    int l = ln >> 2, nb = ln & 3;
    size_t dst = ((size_t)(nb * H + h) * Ldim + l) * HD + d;
    uint32_t h0, l0, h1, l1;
    split2(v.x, v.y, h0, l0);
    split2(v.z, v.w, h1, l1);
    __nv_bfloat16* dh = z ? g_kh : g_qh;
    __nv_bfloat16* dl = z ? g_kl : g_ql;
    *(uint2*)(dh + dst) = make_uint2(h0, h1);
    *(uint2*)(dl + dst) = make_uint2(l0, l1);
}

// ---------------- prep: v -> transposed bf16 hi/lo [bh][d][L] ----------------
__global__ void __launch_bounds__(256) v_prep()
{
    __shared__ float vt[64][65];
    int bh = blockIdx.y;
    int s0 = blockIdx.x * 64;
    int nb = bh / H, h = bh % H;
    int t = threadIdx.x;
    {
        int s = t >> 2, dq = (t & 3) * 16;
        const float* src = g_v + ((size_t)(s0 + s) * Nb + nb) * E + h * HD + dq;
#pragma unroll
        for (int j = 0; j < 4; j++) {
            float4 v = *(const float4*)(src + j * 4);
            vt[s][dq + j * 4 + 0] = v.x;
            vt[s][dq + j * 4 + 1] = v.y;
            vt[s][dq + j * 4 + 2] = v.z;
            vt[s][dq + j * 4 + 3] = v.w;
        }
    }
    __syncthreads();
    {
        int d = t >> 2, sq = (t & 3) * 16;
        uint32_t hw[8], lw[8];
#pragma unroll
        for (int j = 0; j < 8; j++)
            split2(vt[sq + 2 * j][d], vt[sq + 2 * j + 1][d], hw[j], lw[j]);
        size_t dst = ((size_t)bh * HD + d) * Ldim + s0 + sq;
        ((uint4*)(g_vth + dst))[0] = make_uint4(hw[0], hw[1], hw[2], hw[3]);
        ((uint4*)(g_vth + dst))[1] = make_uint4(hw[4], hw[5], hw[6], hw[7]);
        ((uint4*)(g_vtl + dst))[0] = make_uint4(lw[0], lw[1], lw[2], lw[3]);
        ((uint4*)(g_vtl + dst))[1] = make_uint4(lw[4], lw[5], lw[6], lw[7]);
    }
}

// ================= warp-MMA flash attention (bf16 hi/lo 3-pass) ==============
// grid (L/64, BH), 128 threads (4 warps, 16 q-rows each)
#define SKB 144                 /* smem row stride bytes (72 bf16, pad) */
#define SQH 0
#define SQL 9216
#define SKH 18432
#define SKL 27648
#define SVH 36864
#define SVL 46080
#define S_TOTAL 55296

// load a full 64x64 bf16 tile (8192 B): 128 threads x 64 B each
__device__ __forceinline__ void load_tile64(uint32_t dst, const __nv_bfloat16* src,
                                            int tid, int rstride)
{
    int m = tid >> 1;
    int u0 = (tid & 1) * 4;               // uint4 index: 0 or 4 (half-row each)
    const uint4* s = (const uint4*)(src + (size_t)m * rstride) + u0;
    uint4 a = s[0], b = s[1], c = s[2], d = s[3];
    uint32_t o = dst + (uint32_t)m * SKB + (uint32_t)u0 * 16;
    STS128(o,      a.x, a.y, a.z, a.w);
    STS128(o + 16, b.x, b.y, b.z, b.w);
    STS128(o + 32, c.x, c.y, c.z, c.w);
    STS128(o + 48, d.x, d.y, d.z, d.w);
}

__global__ void __launch_bounds__(128) attn_mma()
{
    extern __shared__ __align__(128) char smem[];
    uint32_t sb = smem_u32(smem);
    int tid = threadIdx.x;
    int wid = tid >> 5, lane = tid & 31;
    int bh = blockIdx.y;
    int nb = bh / H, h = bh % H;
    int q0 = blockIdx.x * 64;

    const __nv_bfloat16* qh_src = g_qh + ((size_t)bh * Ldim + q0) * HD;
    const __nv_bfloat16* ql_src = g_ql + ((size_t)bh * Ldim + q0) * HD;
    load_tile64(sb + SQH, qh_src, tid, HD);
    load_tile64(sb + SQL, ql_src, tid, HD);

    // per-lane ldmatrix address components
    int rb = lane & 7;
    uint32_t qrow = (uint32_t)(16 * wid + (lane & 15)) * SKB + (uint32_t)(lane >> 4) * 16;
    uint32_t brow = (uint32_t)(((lane >> 4) * 8 + rb)) * SKB + (uint32_t)((lane >> 3) & 1) * 16;

    float Oa[8][4];
#pragma unroll
    for (int n = 0; n < 8; n++)
#pragma unroll
        for (int j = 0; j < 4; j++) Oa[n][j] = 0.f;
    float m_lo = -INFINITY, m_hi = -INFINITY, l_lo = 0.f, l_hi = 0.f;

    for (int t = 0; t < Ldim / 64; t++) {
        int s0 = t * 64;
        __syncthreads();
        load_tile64(sb + SKH, g_kh + ((size_t)bh * Ldim + s0) * HD, tid, HD);
        load_tile64(sb + SKL, g_kl + ((size_t)bh * Ldim + s0) * HD, tid, HD);
        load_tile64(sb + SVH, g_vth + (size_t)bh * HD * Ldim + s0, tid, Ldim);
        load_tile64(sb + SVL, g_vtl + (size_t)bh * HD * Ldim + s0, tid, Ldim);
        __syncthreads();

        // ---- Q fragments (reloaded each tile to bound register pressure) ---
        uint32_t qfh[4][4], qfl[4][4];
#pragma unroll
        for (int k = 0; k < 4; k++) {
            ldm_x4(qfh[k], sb + SQH + qrow + k * 32);
            ldm_x4(qfl[k], sb + SQL + qrow + k * 32);
        }

        // ---- S = Q K^T (3-pass) --------------------------------------------
        float c[8][4];
#pragma unroll
        for (int n = 0; n < 8; n++)
#pragma unroll
            for (int j = 0; j < 4; j++) c[n][j] = 0.f;
#pragma unroll
        for (int np = 0; np < 4; np++) {
            uint32_t baseH = sb + SKH + brow + np * (2 * 8 * SKB);
            uint32_t baseL = sb + SKL + brow + np * (2 * 8 * SKB);
#pragma unroll
            for (int k = 0; k < 4; k++) {
                uint32_t bhh[4], bll[4];
                ldm_x4(bhh, baseH + k * 32);
                ldm_x4(bll, baseL + k * 32);
                mma16816(c[2 * np],     qfh[k], bhh);
                mma16816(c[2 * np],     qfh[k], bll);
                mma16816(c[2 * np],     qfl[k], bhh);
                mma16816(c[2 * np + 1], qfh[k], bhh + 2);
                mma16816(c[2 * np + 1], qfh[k], bll + 2);
                mma16816(c[2 * np + 1], qfl[k], bhh + 2);
            }
        }

        // ---- online softmax (quad-local rows) -------------------------------
        float mn_lo = m_lo, mn_hi = m_hi;
#pragma unroll
        for (int n = 0; n < 8; n++) {
            mn_lo = fmaxf(mn_lo, fmaxf(c[n][0], c[n][1]));
            mn_hi = fmaxf(mn_hi, fmaxf(c[n][2], c[n][3]));
        }
        mn_lo = fmaxf(mn_lo, __shfl_xor_sync(0xffffffffu, mn_lo, 1));
        mn_lo = fmaxf(mn_lo, __shfl_xor_sync(0xffffffffu, mn_lo, 2));
        mn_hi = fmaxf(mn_hi, __shfl_xor_sync(0xffffffffu, mn_hi, 1));
        mn_hi = fmaxf(mn_hi, __shfl_xor_sync(0xffffffffu, mn_hi, 2));
        float corr_lo = ex2f(m_lo - mn_lo);
        float corr_hi = ex2f(m_hi - mn_hi);
        m_lo = mn_lo; m_hi = mn_hi;
        l_lo *= corr_lo; l_hi *= corr_hi;
#pragma unroll
        for (int n = 0; n < 8; n++) {
            Oa[n][0] *= corr_lo; Oa[n][1] *= corr_lo;
            Oa[n][2] *= corr_hi; Oa[n][3] *= corr_hi;
        }
        // exp + pack P into A-fragments (hi/lo)
        uint32_t ph[4][4], pl[4][4];
#pragma unroll
        for (int n = 0; n < 8; n++) {
            float p0 = ex2f(c[n][0] - mn_lo);
            float p1 = ex2f(c[n][1] - mn_lo);
            float p2 = ex2f(c[n][2] - mn_hi);
            float p3 = ex2f(c[n][3] - mn_hi);
            l_lo += p0 + p1;
            l_hi += p2 + p3;
            uint32_t h01, l01, h23, l23;
            split2(p0, p1, h01, l01);
            split2(p2, p3, h23, l23);
            int kc = n >> 1, o = (n & 1) * 2;
            ph[kc][o] = h01; ph[kc][o + 1] = h23;
            pl[kc][o] = l01; pl[kc][o + 1] = l23;
        }

        // ---- O += P V (3-pass) ----------------------------------------------
#pragma unroll
        for (int np = 0; np < 4; np++) {
            uint32_t baseH = sb + SVH + brow + np * (2 * 8 * SKB);
            uint32_t baseL = sb + SVL + brow + np * (2 * 8 * SKB);
#pragma unroll
            for (int k = 0; k < 4; k++) {
                uint32_t vhh[4], vll[4];
                ldm_x4(vhh, baseH + k * 32);
                ldm_x4(vll, baseL + k * 32);
                mma16816(Oa[2 * np],     ph[k], vhh);
                mma16816(Oa[2 * np],     ph[k], vll);
                mma16816(Oa[2 * np],     pl[k], vhh);
                mma16816(Oa[2 * np + 1], ph[k], vhh + 2);
                mma16816(Oa[2 * np + 1], ph[k], vll + 2);
                mma16816(Oa[2 * np + 1], pl[k], vhh + 2);
            }
        }
    }

    // ---- epilogue -------------------------------------------------------------
    l_lo += __shfl_xor_sync(0xffffffffu, l_lo, 1);
    l_lo += __shfl_xor_sync(0xffffffffu, l_lo, 2);
    l_hi += __shfl_xor_sync(0xffffffffu, l_hi, 1);
    l_hi += __shfl_xor_sync(0xffffffffu, l_hi, 2);
    float inv_lo = 1.f / l_lo, inv_hi = 1.f / l_hi;

    int r = lane >> 2, cc = (lane & 3) * 2;
    float* o_lo = g_o + ((size_t)(q0 + 16 * wid + r) * Nb + nb) * E + h * HD;
    float* o_hi = g_o + ((size_t)(q0 + 16 * wid + r + 8) * Nb + nb) * E + h * HD;
#pragma unroll
    for (int n = 0; n < 8; n++) {
        int d = n * 8 + cc;
        float2 vlo = make_float2(Oa[n][0] * inv_lo, Oa[n][1] * inv_lo);
        float2 vhi = make_float2(Oa[n][2] * inv_hi, Oa[n][3] * inv_hi);
        *(float2*)(o_lo + d) = vlo;
        *(float2*)(o_hi + d) = vhi;
    }
}

// ---------------- launcher ---------------------------------------------------
extern "C" void kernel_launch(void* const* d_in, const int* in_sizes, int n_in,
                              void* d_out, int out_size)
{
    const float* query = (const float*)d_in[0];
    const float* key   = (const float*)d_in[1];
    const float* value = (const float*)d_in[2];
    const float* in_w  = (const float*)d_in[3];
    const float* in_b  = (const float*)d_in[4];
    const float* q_dn  = (const float*)d_in[5];
    const float* q_up  = (const float*)d_in[6];
    const float* k_dn  = (const float*)d_in[7];
    const float* k_up  = (const float*)d_in[8];
    const float* v_dn  = (const float*)d_in[9];
    const float* v_up  = (const float*)d_in[10];
    const float* out_w = (const float*)d_in[11];
    const float* out_b = (const float*)d_in[12];
    const float* o_dn  = (const float*)d_in[13];
    const float* o_up  = (const float*)d_in[14];

    float *p_weff, *p_q, *p_k, *p_v, *p_o;
    cudaGetSymbolAddress((void**)&p_weff, g_weff);
    cudaGetSymbolAddress((void**)&p_q, g_q);
    cudaGetSymbolAddress((void**)&p_k, g_k);
    cudaGetSymbolAddress((void**)&p_v, g_v);
    cudaGetSymbolAddress((void**)&p_o, g_o);

    cudaFuncSetAttribute(attn_mma,
                         cudaFuncAttributeMaxDynamicSharedMemorySize, S_TOTAL);

    // 1) fold LoRA into effective weights
    weff_kernel<<<dim3(EE / 256, 4), 256>>>(in_w, out_w,
                                            q_dn, q_up, k_dn, k_up,
                                            v_dn, v_up, o_dn, o_up);
    // 2) q,k,v projections (q pre-scaled by 0.125*log2e)
    gemm_proj<<<dim3(E / 128, Mrows / 128, 3), 256>>>(
        query, key, value, p_weff, in_b, p_q, p_k, p_v, /*qz=*/0);
    // 3) bf16 hi/lo split prep
    qk_prep<<<dim3(Mrows * E / 4 / 256, 1, 2), 256>>>();
    v_prep<<<dim3(Ldim / 64, BH), 256>>>();
    // 4) warp-MMA flash attention
    attn_mma<<<dim3(Ldim / 64, BH), 128, S_TOTAL>>>();
    // 5) output projection -> d_out
    gemm_proj<<<dim3(E / 128, Mrows / 128, 1), 256>>>(
        p_o, p_o, p_o, p_weff + 3 * (size_t)EE, out_b,
        (float*)d_out, (float*)d_out, (float*)d_out, /*qz=*/-1);
}

// round 5
// speedup vs baseline: 1.7871x; 1.0350x over previous
#include <cuda_runtime.h>
#include <cuda_bf16.h>
#include <math.h>
#include <stdint.h>

#define Ldim 2048
#define Nb   4
#define E    768
#define H    12
#define HD   64
#define BH   (Nb*H)         /* 48 */
#define Mrows (Ldim*Nb)     /* 8192 */
#define EE   (E*E)          /* 589824 */

// ---------------- scratch (static device globals; no runtime allocation) ----
__device__ float g_weff[4*EE];
__device__ float g_q[Mrows*E];
__device__ float g_k[Mrows*E];
__device__ float g_v[Mrows*E];
__device__ float g_o[Mrows*E];
// bf16 hi/lo split buffers: q,k as [bh][l][64]; v transposed as [bh][d][L]
__device__ __nv_bfloat16 g_qh[BH*Ldim*HD], g_ql[BH*Ldim*HD];
__device__ __nv_bfloat16 g_kh[BH*Ldim*HD], g_kl[BH*Ldim*HD];
__device__ __nv_bfloat16 g_vth[BH*HD*Ldim], g_vtl[BH*HD*Ldim];

// ============================ helpers ========================================
__device__ __forceinline__ uint32_t smem_u32(const void* p) {
    uint32_t a;
    asm("{ .reg .u64 t; cvta.to.shared.u64 t, %1; cvt.u32.u64 %0, t; }"
        : "=r"(a) : "l"(p));
    return a;
}
__device__ __forceinline__ float ex2f(float x) {
    float y; asm("ex2.approx.f32 %0, %1;" : "=f"(y) : "f"(x)); return y;
}
#define STS128(addr, r0, r1, r2, r3) \
    asm volatile("st.shared.v4.b32 [%0], {%1, %2, %3, %4};" \
                 :: "r"(addr), "r"(r0), "r"(r1), "r"(r2), "r"(r3) : "memory")

__device__ __forceinline__ void cpa16(uint32_t dst, const void* src) {
    asm volatile("cp.async.cg.shared.global [%0], [%1], 16;"
                 :: "r"(dst), "l"(src) : "memory");
}
#define CP_COMMIT() asm volatile("cp.async.commit_group;" ::: "memory")
#define CP_WAIT1()  asm volatile("cp.async.wait_group 1;" ::: "memory")
#define CP_WAIT0()  asm volatile("cp.async.wait_group 0;" ::: "memory")

__device__ __forceinline__ void ldm_x4(uint32_t* r, uint32_t addr) {
    asm volatile("ldmatrix.sync.aligned.m8n8.x4.shared.b16 {%0,%1,%2,%3}, [%4];"
                 : "=r"(r[0]), "=r"(r[1]), "=r"(r[2]), "=r"(r[3]) : "r"(addr));
}
__device__ __forceinline__ void mma16816(float* c, const uint32_t* a,
                                         const uint32_t* b) {
    asm volatile(
        "mma.sync.aligned.m16n8k16.row.col.f32.bf16.bf16.f32 "
        "{%0,%1,%2,%3}, {%4,%5,%6,%7}, {%8,%9}, {%0,%1,%2,%3};"
        : "+f"(c[0]), "+f"(c[1]), "+f"(c[2]), "+f"(c[3])
        : "r"(a[0]), "r"(a[1]), "r"(a[2]), "r"(a[3]), "r"(b[0]), "r"(b[1]));
}
// split a pair of floats into bf16 hi and lo packed words (elem0 in low bits)
__device__ __forceinline__ void split2(float a, float b, uint32_t& hi, uint32_t& lo) {
    __nv_bfloat162 h = __floats2bfloat162_rn(a, b);
    float la = a - __bfloat162float(h.x);
    float lb = b - __bfloat162float(h.y);
    __nv_bfloat162 l = __floats2bfloat162_rn(la, lb);
    hi = *reinterpret_cast<uint32_t*>(&h);
    lo = *reinterpret_cast<uint32_t*>(&l);
}

// ---------------- W_eff = W + up @ down -------------------------------------
__global__ void weff_kernel(const float* __restrict__ inW,
                            const float* __restrict__ outW,
                            const float* __restrict__ qd, const float* __restrict__ qu,
                            const float* __restrict__ kd, const float* __restrict__ ku,
                            const float* __restrict__ vd, const float* __restrict__ vu,
                            const float* __restrict__ od, const float* __restrict__ ou)
{
    int z = blockIdx.y;
    int idx = blockIdx.x * 256 + threadIdx.x;
    int e = idx / E;
    int k = idx - e * E;
    const float* W  = (z < 3) ? (inW + z * EE) : outW;
    const float* dn = (z == 0) ? qd : (z == 1) ? kd : (z == 2) ? vd : od;
    const float* up = (z == 0) ? qu : (z == 1) ? ku : (z == 2) ? vu : ou;
    float s = 0.f;
#pragma unroll
    for (int r = 0; r < 16; r++) s += up[e * 16 + r] * dn[r * E + k];
    g_weff[z * EE + idx] = W[idx] + s;
}

// ---------------- 128x128x8 register-tiled fp32 GEMM ------------------------
__global__ void __launch_bounds__(256, 2) gemm_proj(
    const float* __restrict__ x0, const float* __restrict__ x1, const float* __restrict__ x2,
    const float* __restrict__ Wbase, const float* __restrict__ bias_base,
    float* __restrict__ y0, float* __restrict__ y1, float* __restrict__ y2,
    int qz)
{
    int z = blockIdx.z;
    const float* x = (z == 0) ? x0 : (z == 1) ? x1 : x2;
    float*       y = (z == 0) ? y0 : (z == 1) ? y1 : y2;
    const float* W = Wbase + (size_t)z * EE;
    const float* bias = bias_base + z * E;

    int m0 = blockIdx.y * 128;
    int e0 = blockIdx.x * 128;

    __shared__ float As[8][128];
    __shared__ float Bs[8][128];

    float acc[8][8];
#pragma unroll
    for (int i = 0; i < 8; i++)
#pragma unroll
        for (int j = 0; j < 8; j++) acc[i][j] = 0.f;

    int tid = threadIdx.x;
    int lr = tid >> 1;
    int lc = (tid & 1) * 4;
    int ty = tid >> 4, tx = tid & 15;

    for (int k0 = 0; k0 < E; k0 += 8) {
        float4 av = *(const float4*)(x + (size_t)(m0 + lr) * E + k0 + lc);
        float4 bv = *(const float4*)(W + (size_t)(e0 + lr) * E + k0 + lc);
        __syncthreads();
        As[lc + 0][lr] = av.x; As[lc + 1][lr] = av.y; As[lc + 2][lr] = av.z; As[lc + 3][lr] = av.w;
        Bs[lc + 0][lr] = bv.x; Bs[lc + 1][lr] = bv.y; Bs[lc + 2][lr] = bv.z; Bs[lc + 3][lr] = bv.w;
        __syncthreads();
#pragma unroll
        for (int kt = 0; kt < 8; kt++) {
            float a[8], b[8];
            float4 t;
            t = *(const float4*)&As[kt][ty * 4];      a[0]=t.x; a[1]=t.y; a[2]=t.z; a[3]=t.w;
            t = *(const float4*)&As[kt][64 + ty * 4]; a[4]=t.x; a[5]=t.y; a[6]=t.z; a[7]=t.w;
            t = *(const float4*)&Bs[kt][tx * 4];      b[0]=t.x; b[1]=t.y; b[2]=t.z; b[3]=t.w;
            t = *(const float4*)&Bs[kt][64 + tx * 4]; b[4]=t.x; b[5]=t.y; b[6]=t.z; b[7]=t.w;
#pragma unroll
            for (int i = 0; i < 8; i++)
#pragma unroll
                for (int j = 0; j < 8; j++) acc[i][j] += a[i] * b[j];
        }
    }

    float qs = (z == qz) ? 0.125f * 1.4426950408889634f : 1.0f; // fold scale*log2e into q
#pragma unroll
    for (int i = 0; i < 8; i++) {
        int row = m0 + ((i < 4) ? (ty * 4 + i) : (64 + ty * 4 + i - 4));
#pragma unroll
        for (int j = 0; j < 8; j++) {
            int col = e0 + ((j < 4) ? (tx * 4 + j) : (64 + tx * 4 + j - 4));
            y[(size_t)row * E + col] = (acc[i][j] + bias[col]) * qs;
        }
    }
}

// ---------------- prep: q,k -> bf16 hi/lo [bh][l][64] ------------------------
__global__ void __launch_bounds__(256) qk_prep()
{
    int z = blockIdx.z;
    size_t idx = (size_t)blockIdx.x * 256 + threadIdx.x;  // float4 index
    const float4* src = (const float4*)(z ? g_k : g_q);
    float4 v = src[idx];
    int e4 = (int)(idx % (E / 4));
    int ln = (int)(idx / (E / 4));          // l*Nb + nb
    int e = e4 * 4, h = e >> 6, d = e & 63;
    int l = ln >> 2, nb = ln & 3;
    size_t dst = ((size_t)(nb * H + h) * Ldim + l) * HD + d;
    uint32_t h0, l0, h1, l1;
    split2(v.x, v.y, h0, l0);
    split2(v.z, v.w, h1, l1);
    __nv_bfloat16* dh = z ? g_kh : g_qh;
    __nv_bfloat16* dl = z ? g_kl : g_ql;
    *(uint2*)(dh + dst) = make_uint2(h0, h1);
    *(uint2*)(dl + dst) = make_uint2(l0, l1);
}

// ---------------- prep: v -> transposed bf16 hi/lo [bh][d][L] ----------------
__global__ void __launch_bounds__(256) v_prep()
{
    __shared__ float vt[64][65];
    int bh = blockIdx.y;
    int s0 = blockIdx.x * 64;
    int nb = bh / H, h = bh % H;
    int t = threadIdx.x;
    {
        int s = t >> 2, dq = (t & 3) * 16;
        const float* src = g_v + ((size_t)(s0 + s) * Nb + nb) * E + h * HD + dq;
#pragma unroll
        for (int j = 0; j < 4; j++) {
            float4 v = *(const float4*)(src + j * 4);
            vt[s][dq + j * 4 + 0] = v.x;
            vt[s][dq + j * 4 + 1] = v.y;
            vt[s][dq + j * 4 + 2] = v.z;
            vt[s][dq + j * 4 + 3] = v.w;
        }
    }
    __syncthreads();
    {
        int d = t >> 2, sq = (t & 3) * 16;
        uint32_t hw[8], lw[8];
#pragma unroll
        for (int j = 0; j < 8; j++)
            split2(vt[sq + 2 * j][d], vt[sq + 2 * j + 1][d], hw[j], lw[j]);
        size_t dst = ((size_t)bh * HD + d) * Ldim + s0 + sq;
        ((uint4*)(g_vth + dst))[0] = make_uint4(hw[0], hw[1], hw[2], hw[3]);
        ((uint4*)(g_vth + dst))[1] = make_uint4(hw[4], hw[5], hw[6], hw[7]);
        ((uint4*)(g_vtl + dst))[0] = make_uint4(lw[0], lw[1], lw[2], lw[3]);
        ((uint4*)(g_vtl + dst))[1] = make_uint4(lw[4], lw[5], lw[6], lw[7]);
    }
}

// ================= warp-MMA flash attention, pipelined =======================
// grid (L/128, BH), 256 threads (8 warps, 16 q-rows each), BS=64,
// cp.async double-buffered KV.
#define SKB 144                 /* smem row stride bytes (72 bf16, pad) */
#define SQH 0
#define SQL 18432
#define SKV0 36864
#define STAGE_B 36864
#define KH_O 0
#define KL_O 9216
#define VH_O 18432
#define VL_O 27648
#define S_TOTAL2 110592
#define NT (Ldim / 64)

__device__ __forceinline__ void kv_prefetch(uint32_t buf, int bh, int s0, int tid)
{
    int m = tid >> 2, j = tid & 3;
    uint32_t ro = (uint32_t)m * SKB + (uint32_t)j * 32;
    const __nv_bfloat16* kh = g_kh + ((size_t)bh * Ldim + s0 + m) * HD + j * 16;
    const __nv_bfloat16* kl = g_kl + ((size_t)bh * Ldim + s0 + m) * HD + j * 16;
    const __nv_bfloat16* vh = g_vth + ((size_t)bh * HD + m) * Ldim + s0 + j * 16;
    const __nv_bfloat16* vl = g_vtl + ((size_t)bh * HD + m) * Ldim + s0 + j * 16;
    cpa16(buf + KH_O + ro,      kh);
    cpa16(buf + KH_O + ro + 16, kh + 8);
    cpa16(buf + KL_O + ro,      kl);
    cpa16(buf + KL_O + ro + 16, kl + 8);
    cpa16(buf + VH_O + ro,      vh);
    cpa16(buf + VH_O + ro + 16, vh + 8);
    cpa16(buf + VL_O + ro,      vl);
    cpa16(buf + VL_O + ro + 16, vl + 8);
}

__global__ void __launch_bounds__(256) attn_mma2()
{
    extern __shared__ __align__(128) char smem[];
    uint32_t sb = smem_u32(smem);
    int tid = threadIdx.x;
    int wid = tid >> 5, lane = tid & 31;
    int bh = blockIdx.y;
    int nb = bh / H, h = bh % H;
    int q0 = blockIdx.x * 128;

    // kick off stage 0 KV prefetch
    kv_prefetch(sb + SKV0, bh, 0, tid);
    CP_COMMIT();

    // load Q (128 rows x 64, hi+lo) to smem: 256 threads x 64B per tile
    {
        int m = tid >> 1;
        int u0 = (tid & 1) * 4;
        uint32_t o = (uint32_t)m * SKB + (uint32_t)u0 * 16;
        const uint4* s = (const uint4*)(g_qh + ((size_t)bh * Ldim + q0 + m) * HD) + u0;
        uint4 a = s[0], b = s[1], c = s[2], d = s[3];
        STS128(sb + SQH + o,      a.x, a.y, a.z, a.w);
        STS128(sb + SQH + o + 16, b.x, b.y, b.z, b.w);
        STS128(sb + SQH + o + 32, c.x, c.y, c.z, c.w);
        STS128(sb + SQH + o + 48, d.x, d.y, d.z, d.w);
        s = (const uint4*)(g_ql + ((size_t)bh * Ldim + q0 + m) * HD) + u0;
        a = s[0]; b = s[1]; c = s[2]; d = s[3];
        STS128(sb + SQL + o,      a.x, a.y, a.z, a.w);
        STS128(sb + SQL + o + 16, b.x, b.y, b.z, b.w);
        STS128(sb + SQL + o + 32, c.x, c.y, c.z, c.w);
        STS128(sb + SQL + o + 48, d.x, d.y, d.z, d.w);
    }
    __syncthreads();

    // per-lane ldmatrix address components
    uint32_t qrow = (uint32_t)(16 * wid + (lane & 15)) * SKB + (uint32_t)(lane >> 4) * 16;
    uint32_t brow = (uint32_t)(((lane >> 4) * 8 + (lane & 7))) * SKB
                  + (uint32_t)((lane >> 3) & 1) * 16;

    // Q fragments held in registers for the whole loop
    uint32_t qfh[4][4], qfl[4][4];
#pragma unroll
    for (int k = 0; k < 4; k++) {
        ldm_x4(qfh[k], sb + SQH + qrow + k * 32);
        ldm_x4(qfl[k], sb + SQL + qrow + k * 32);
    }

    float Oa[8][4];
#pragma unroll
    for (int n = 0; n < 8; n++)
#pragma unroll
        for (int j = 0; j < 4; j++) Oa[n][j] = 0.f;
    float m_lo = -INFINITY, m_hi = -INFINITY, l_lo = 0.f, l_hi = 0.f;

    for (int t = 0; t < NT; t++) {
        uint32_t cb = sb + SKV0 + (uint32_t)(t & 1) * STAGE_B;
        if (t + 1 < NT) {
            kv_prefetch(sb + SKV0 + (uint32_t)((t + 1) & 1) * STAGE_B,
                        bh, (t + 1) * 64, tid);
            CP_COMMIT();
            CP_WAIT1();
        } else {
            CP_WAIT0();
        }
        __syncthreads();

        // ---- S = Q K^T (3-pass) --------------------------------------------
        float c[8][4];
#pragma unroll
        for (int n = 0; n < 8; n++)
#pragma unroll
            for (int j = 0; j < 4; j++) c[n][j] = 0.f;
#pragma unroll
        for (int np = 0; np < 4; np++) {
            uint32_t baseH = cb + KH_O + brow + np * (16 * SKB);
            uint32_t baseL = cb + KL_O + brow + np * (16 * SKB);
#pragma unroll
            for (int k = 0; k < 4; k++) {
                uint32_t bhh[4], bll[4];
                ldm_x4(bhh, baseH + k * 32);
                ldm_x4(bll, baseL + k * 32);
                mma16816(c[2 * np],     qfh[k], bhh);
                mma16816(c[2 * np],     qfh[k], bll);
                mma16816(c[2 * np],     qfl[k], bhh);
                mma16816(c[2 * np + 1], qfh[k], bhh + 2);
                mma16816(c[2 * np + 1], qfh[k], bll + 2);
                mma16816(c[2 * np + 1], qfl[k], bhh + 2);
            }
        }

        // ---- online softmax (quad-local rows) -------------------------------
        float mn_lo = m_lo, mn_hi = m_hi;
#pragma unroll
        for (int n = 0; n < 8; n++) {
            mn_lo = fmaxf(mn_lo, fmaxf(c[n][0], c[n][1]));
            mn_hi = fmaxf(mn_hi, fmaxf(c[n][2], c[n][3]));
        }
        mn_lo = fmaxf(mn_lo, __shfl_xor_sync(0xffffffffu, mn_lo, 1));
        mn_lo = fmaxf(mn_lo, __shfl_xor_sync(0xffffffffu, mn_lo, 2));
        mn_hi = fmaxf(mn_hi, __shfl_xor_sync(0xffffffffu, mn_hi, 1));
        mn_hi = fmaxf(mn_hi, __shfl_xor_sync(0xffffffffu, mn_hi, 2));
        float corr_lo = ex2f(m_lo - mn_lo);
        float corr_hi = ex2f(m_hi - mn_hi);
        m_lo = mn_lo; m_hi = mn_hi;
        l_lo *= corr_lo; l_hi *= corr_hi;
#pragma unroll
        for (int n = 0; n < 8; n++) {
            Oa[n][0] *= corr_lo; Oa[n][1] *= corr_lo;
            Oa[n][2] *= corr_hi; Oa[n][3] *= corr_hi;
        }
        // exp + pack P into A-fragments (hi/lo)
        uint32_t ph[4][4], pl[4][4];
#pragma unroll
        for (int n = 0; n < 8; n++) {
            float p0 = ex2f(c[n][0] - mn_lo);
            float p1 = ex2f(c[n][1] - mn_lo);
            float p2 = ex2f(c[n][2] - mn_hi);
            float p3 = ex2f(c[n][3] - mn_hi);
            l_lo += p0 + p1;
            l_hi += p2 + p3;
            uint32_t h01, l01, h23, l23;
            split2(p0, p1, h01, l01);
            split2(p2, p3, h23, l23);
            int kc = n >> 1, o = (n & 1) * 2;
            ph[kc][o] = h01; ph[kc][o + 1] = h23;
            pl[kc][o] = l01; pl[kc][o + 1] = l23;
        }

        // ---- O += P V (3-pass) ----------------------------------------------
#pragma unroll
        for (int np = 0; np < 4; np++) {
            uint32_t baseH = cb + VH_O + brow + np * (16 * SKB);
            uint32_t baseL = cb + VL_O + brow + np * (16 * SKB);
#pragma unroll
            for (int k = 0; k < 4; k++) {
                uint32_t vhh[4], vll[4];
                ldm_x4(vhh, baseH + k * 32);
                ldm_x4(vll, baseL + k * 32);
                mma16816(Oa[2 * np],     ph[k], vhh);
                mma16816(Oa[2 * np],     ph[k], vll);
                mma16816(Oa[2 * np],     pl[k], vhh);
                mma16816(Oa[2 * np + 1], ph[k], vhh + 2);
                mma16816(Oa[2 * np + 1], ph[k], vll + 2);
                mma16816(Oa[2 * np + 1], pl[k], vhh + 2);
            }
        }
        __syncthreads();
    }

    // ---- epilogue -------------------------------------------------------------
    l_lo += __shfl_xor_sync(0xffffffffu, l_lo, 1);
    l_lo += __shfl_xor_sync(0xffffffffu, l_lo, 2);
    l_hi += __shfl_xor_sync(0xffffffffu, l_hi, 1);
    l_hi += __shfl_xor_sync(0xffffffffu, l_hi, 2);
    float inv_lo = 1.f / l_lo, inv_hi = 1.f / l_hi;

    int r = lane >> 2, cc = (lane & 3) * 2;
    float* o_lo = g_o + ((size_t)(q0 + 16 * wid + r) * Nb + nb) * E + h * HD;
    float* o_hi = g_o + ((size_t)(q0 + 16 * wid + r + 8) * Nb + nb) * E + h * HD;
#pragma unroll
    for (int n = 0; n < 8; n++) {
        int d = n * 8 + cc;
        float2 vlo = make_float2(Oa[n][0] * inv_lo, Oa[n][1] * inv_lo);
        float2 vhi = make_float2(Oa[n][2] * inv_hi, Oa[n][3] * inv_hi);
        *(float2*)(o_lo + d) = vlo;
        *(float2*)(o_hi + d) = vhi;
    }
}

// ---------------- launcher ---------------------------------------------------
extern "C" void kernel_launch(void* const* d_in, const int* in_sizes, int n_in,
                              void* d_out, int out_size)
{
    const float* query = (const float*)d_in[0];
    const float* key   = (const float*)d_in[1];
    const float* value = (const float*)d_in[2];
    const float* in_w  = (const float*)d_in[3];
    const float* in_b  = (const float*)d_in[4];
    const float* q_dn  = (const float*)d_in[5];
    const float* q_up  = (const float*)d_in[6];
    const float* k_dn  = (const float*)d_in[7];
    const float* k_up  = (const float*)d_in[8];
    const float* v_dn  = (const float*)d_in[9];
    const float* v_up  = (const float*)d_in[10];
    const float* out_w = (const float*)d_in[11];
    const float* out_b = (const float*)d_in[12];
    const float* o_dn  = (const float*)d_in[13];
    const float* o_up  = (const float*)d_in[14];

    float *p_weff, *p_q, *p_k, *p_v, *p_o;
    cudaGetSymbolAddress((void**)&p_weff, g_weff);
    cudaGetSymbolAddress((void**)&p_q, g_q);
    cudaGetSymbolAddress((void**)&p_k, g_k);
    cudaGetSymbolAddress((void**)&p_v, g_v);
    cudaGetSymbolAddress((void**)&p_o, g_o);

    cudaFuncSetAttribute(attn_mma2,
                         cudaFuncAttributeMaxDynamicSharedMemorySize, S_TOTAL2);

    // 1) fold LoRA into effective weights
    weff_kernel<<<dim3(EE / 256, 4), 256>>>(in_w, out_w,
                                            q_dn, q_up, k_dn, k_up,
                                            v_dn, v_up, o_dn, o_up);
    // 2) q,k,v projections (q pre-scaled by 0.125*log2e)
    gemm_proj<<<dim3(E / 128, Mrows / 128, 3), 256>>>(
        query, key, value, p_weff, in_b, p_q, p_k, p_v, /*qz=*/0);
    // 3) bf16 hi/lo split prep
    qk_prep<<<dim3(Mrows * E / 4 / 256, 1, 2), 256>>>();
    v_prep<<<dim3(Ldim / 64, BH), 256>>>();
    // 4) pipelined warp-MMA flash attention
    attn_mma2<<<dim3(Ldim / 128, BH), 256, S_TOTAL2>>>();
    // 5) output projection -> d_out
    gemm_proj<<<dim3(E / 128, Mrows / 128, 1), 256>>>(
        p_o, p_o, p_o, p_weff + 3 * (size_t)EE, out_b,
        (float*)d_out, (float*)d_out, (float*)d_out, /*qz=*/-1);
}